// round 7
// baseline (speedup 1.0000x reference)
#include <cuda_runtime.h>
#include <math.h>

// Problem constants
#define NLAT 361
#define NLON 720
#define MMAX 361            // NLON/2 + 1
#define LMAX 360            // NLAT - 1
#define BC   128            // batch*chan
#define NROWS (BC * NLAT)   // 46208 = 361 * 128

#define X_ELEMS  (BC * NLAT * NLON)         // 33,269,760
#define W_ELEMS  (MMAX * LMAX * NLAT)       // 46,915,560
#define TRIG_ELEMS (NLON * MMAX)            // 259,920
#define OUT_REAL (BC * LMAX * MMAX)         // 16,634,880 float32 (real part)

// m processed in chunks to keep static scratch small
#define MCH 32
#define NCHUNK ((MMAX + MCH - 1) / MCH)     // 12
#define XFCH ((size_t)MCH * NROWS)          // 1,478,656 floats per component

// -------- static device scratch --------
__device__ float sht_cos[TRIG_ELEMS];
__device__ float sht_sin[TRIG_ELEMS];
__device__ float sht_xfr[XFCH];   // [m_local][r], r = bc*361 + k
__device__ float sht_xfi[XFCH];

// ---------------------------------------------------------------
__global__ void sht_init_trig() {
    int idx = blockIdx.x * blockDim.x + threadIdx.x;
    if (idx >= TRIG_ELEMS) return;
    int n = idx / MMAX;
    int m = idx - n * MMAX;
    int r = (n * m) % NLON;
    double theta = 6.283185307179586476925286766559 * (double)r / (double)NLON;
    const double scale = 6.283185307179586476925286766559 / (double)NLON;
    sht_cos[idx] = (float)(cos(theta) * scale);
    sht_sin[idx] = (float)(-sin(theta) * scale);
}

// ---------------------------------------------------------------
// Stage 1 (per m-chunk): xf[ml][r] = sum_n x[r][n]*trig[n][mbase+ml]
// BM=128 rows, BN=32 m, BK=16; 256 threads, 8x2 microtile. grid=(361)
// ---------------------------------------------------------------
__global__ __launch_bounds__(256) void sht_stage1(const float* __restrict__ x,
                                                  unsigned xbud, int mbase) {
    __shared__ float As[16][132];
    __shared__ float Bc[16][36];
    __shared__ float Bs[16][36];

    const int tid  = threadIdx.x;
    const int row0 = blockIdx.x * 128;
    const int tx   = tid & 15;
    const int ty   = tid >> 4;

    float aC[2][8], aS[2][8];
#pragma unroll
    for (int j = 0; j < 2; j++)
#pragma unroll
        for (int i = 0; i < 8; i++) { aC[j][i] = 0.f; aS[j][i] = 0.f; }

    for (int kb = 0; kb < NLON; kb += 16) {
#pragma unroll
        for (int i = 0; i < 8; i++) {
            int f   = tid + i * 256;
            int row = f >> 4;
            int kk  = f & 15;
            unsigned gi = (unsigned)(row0 + row) * NLON + (unsigned)(kb + kk);
            As[kk][row] = (gi < xbud) ? x[gi] : 0.f;
        }
#pragma unroll
        for (int i = 0; i < 2; i++) {
            int f = tid + i * 256;
            int r = f >> 5;
            int c = f & 31;
            int m = mbase + c;
            float vc = 0.f, vs = 0.f;
            if (m < MMAX) {
                int gi = (kb + r) * MMAX + m;
                vc = sht_cos[gi];
                vs = sht_sin[gi];
            }
            Bc[r][c] = vc;
            Bs[r][c] = vs;
        }
        __syncthreads();

#pragma unroll
        for (int kk = 0; kk < 16; kk++) {
            float a[8];
#pragma unroll
            for (int i = 0; i < 8; i++) a[i] = As[kk][ty * 8 + i];
            float c0 = Bc[kk][tx * 2], c1 = Bc[kk][tx * 2 + 1];
            float s0 = Bs[kk][tx * 2], s1 = Bs[kk][tx * 2 + 1];
#pragma unroll
            for (int i = 0; i < 8; i++) {
                aC[0][i] = fmaf(a[i], c0, aC[0][i]);
                aC[1][i] = fmaf(a[i], c1, aC[1][i]);
                aS[0][i] = fmaf(a[i], s0, aS[0][i]);
                aS[1][i] = fmaf(a[i], s1, aS[1][i]);
            }
        }
        __syncthreads();
    }

#pragma unroll
    for (int j = 0; j < 2; j++) {
        int ml = tx * 2 + j;
        int m  = mbase + ml;
        if (m >= MMAX) continue;
        size_t base = (size_t)ml * NROWS + row0 + ty * 8;
#pragma unroll
        for (int i = 0; i < 8; i++) {
            if (base + i < XFCH) {
                sht_xfr[base + i] = aC[j][i];
                sht_xfi[base + i] = aS[j][i];
            }
        }
    }
}

// ---------------------------------------------------------------
// Stage 2 (per m-chunk): out[bc][l][mbase+ml] = sum_k xf[ml][bc,k]*w[m,l,k]
// Output: REAL PART ONLY as float32 (harness materializes complex64
// reference via astype(float32) -> real part, out_size = 16,634,880).
// BM=128 bc, BN=64 l, BK=16; 256 threads, 8x4 microtile. grid=(6,32)
// ---------------------------------------------------------------
__global__ __launch_bounds__(256) void sht_stage2(const float* __restrict__ w,
                                                  float* __restrict__ out,
                                                  unsigned wbud, unsigned obud,
                                                  int mbase) {
    const int ml = blockIdx.y;
    const int m  = mbase + ml;
    if (m >= MMAX) return;   // uniform over block

    __shared__ float Ar[16][132];
    __shared__ float Ai[16][132];
    __shared__ float Ws[16][68];

    const int tid = threadIdx.x;
    const int l0  = blockIdx.x * 64;
    const int tx  = tid & 15;
    const int ty  = tid >> 4;

    float accR[4][8], accI[4][8];
#pragma unroll
    for (int j = 0; j < 4; j++)
#pragma unroll
        for (int i = 0; i < 8; i++) { accR[j][i] = 0.f; accI[j][i] = 0.f; }

    for (int kb = 0; kb < NLAT; kb += 16) {
#pragma unroll
        for (int i = 0; i < 8; i++) {
            int f  = tid + i * 256;
            int bc = f >> 4;
            int kk = f & 15;
            int k  = kb + kk;
            float vr = 0.f, vi = 0.f;
            if (k < NLAT) {
                size_t gi = (size_t)ml * NROWS + (size_t)bc * NLAT + (size_t)k;
                if (gi < XFCH) { vr = sht_xfr[gi]; vi = sht_xfi[gi]; }
            }
            Ar[kk][bc] = vr;
            Ai[kk][bc] = vi;
        }
#pragma unroll
        for (int i = 0; i < 4; i++) {
            int f  = tid + i * 256;
            int l  = f >> 4;
            int kk = f & 15;
            int k  = kb + kk;
            int ll = l0 + l;
            float v = 0.f;
            if (k < NLAT && ll < LMAX) {
                unsigned gi = (unsigned)m * (LMAX * NLAT) + (unsigned)ll * NLAT + (unsigned)k;
                if (gi < wbud) v = w[gi];
            }
            Ws[kk][l] = v;
        }
        __syncthreads();

#pragma unroll
        for (int kk = 0; kk < 16; kk++) {
            float ar[8], ai[8], wv[4];
#pragma unroll
            for (int i = 0; i < 8; i++) { ar[i] = Ar[kk][ty * 8 + i]; ai[i] = Ai[kk][ty * 8 + i]; }
#pragma unroll
            for (int j = 0; j < 4; j++) wv[j] = Ws[kk][tx * 4 + j];
#pragma unroll
            for (int j = 0; j < 4; j++)
#pragma unroll
                for (int i = 0; i < 8; i++) {
                    accR[j][i] = fmaf(ar[i], wv[j], accR[j][i]);
                    accI[j][i] = fmaf(ai[i], wv[j], accI[j][i]);
                }
        }
        __syncthreads();
    }

    // Store REAL PART ONLY: out[(bc*360 + l)*361 + m], one float each.
#pragma unroll
    for (int j = 0; j < 4; j++) {
        int l = l0 + tx * 4 + j;
        if (l >= LMAX) continue;
#pragma unroll
        for (int i = 0; i < 8; i++) {
            int bc = ty * 8 + i;
            unsigned ci = ((unsigned)bc * LMAX + (unsigned)l) * MMAX + (unsigned)m;
            if (ci < obud) out[ci] = accR[j][i];
        }
    }
}

// ---------------------------------------------------------------
extern "C" void kernel_launch(void* const* d_in, const int* in_sizes, int n_in,
                              void* d_out, int out_size) {
    const float* x = nullptr;
    const float* w = nullptr;
    unsigned xbud = 0, wbud = 0;

    for (int i = 0; i < n_in; i++) {
        if (in_sizes[i] == X_ELEMS && !x) { x = (const float*)d_in[i]; xbud = X_ELEMS; }
        else if (in_sizes[i] == W_ELEMS && !w) { w = (const float*)d_in[i]; wbud = W_ELEMS; }
    }
    for (int i = 0; i < n_in; i++) {
        if (!x && in_sizes[i] == X_ELEMS * 4) { x = (const float*)d_in[i]; xbud = X_ELEMS; }
        else if (!w && in_sizes[i] == W_ELEMS * 4) { w = (const float*)d_in[i]; wbud = W_ELEMS; }
    }
    if (!x && n_in >= 1) {
        x = (const float*)d_in[0];
        long s = in_sizes[0];
        xbud = (unsigned)((s > 0 && s < (long)X_ELEMS) ? s : X_ELEMS);
    }
    if (!w && n_in >= 2) {
        w = (const float*)d_in[1];
        long s = in_sizes[1];
        wbud = (unsigned)((s > 0 && s < (long)W_ELEMS) ? s : W_ELEMS);
    }

    // Output budget in FLOATS, never exceeding out_size (confirmed: the
    // buffer is out_size * 4 bytes; out_size == 16,634,880 == real-part count).
    unsigned obud;
    if (out_size <= 0) obud = OUT_REAL;
    else obud = ((unsigned)out_size < (unsigned)OUT_REAL) ? (unsigned)out_size
                                                          : (unsigned)OUT_REAL;

    float* out = (float*)d_out;

    sht_init_trig<<<(TRIG_ELEMS + 255) / 256, 256>>>();
    for (int c = 0; c < NCHUNK; c++) {
        int mbase = c * MCH;
        sht_stage1<<<dim3(361), 256>>>(x, xbud, mbase);
        sht_stage2<<<dim3(6, MCH), 256>>>(w, out, wbud, obud, mbase);
    }
}

// round 8
// speedup vs baseline: 3.5655x; 3.5655x over previous
#include <cuda_runtime.h>
#include <math.h>

// Problem constants
#define NLAT 361
#define NLON 720
#define MMAX 361            // NLON/2 + 1
#define LMAX 360            // NLAT - 1
#define BC   128            // batch*chan
#define NROWS (BC * NLAT)   // 46208 = 361 * 128

#define X_ELEMS  (BC * NLAT * NLON)         // 33,269,760
#define W_ELEMS  (MMAX * LMAX * NLAT)       // 46,915,560
#define OUT_REAL (BC * LMAX * MMAX)         // 16,634,880 float32 (real part)

#define K1  361             // folded DFT length (0..360)
#define K1P 368             // padded to multiple of 16 (zeros in pad)

// -------- static device scratch (zero-initialized at load) --------
__device__ float sht_trig[K1P * MMAX];            // [n'][m], cos*scale, pad=0
__device__ float sht_xe[(size_t)NROWS * K1P];     // folded input [r][368]
__device__ float sht_xfr[(size_t)MMAX * BC * K1P];// [m][bc][368] real spectra

// ---------------------------------------------------------------
// Trig table: cos(2*pi*n*m/720) * (2*pi/720), exact integer reduction.
// ---------------------------------------------------------------
__global__ void sht_init_trig() {
    int idx = blockIdx.x * blockDim.x + threadIdx.x;
    if (idx >= K1P * MMAX) return;
    int n = idx / MMAX;
    int m = idx - n * MMAX;
    float v = 0.f;
    if (n <= 360) {
        int r = (n * m) % NLON;
        double theta = 6.283185307179586476925286766559 * (double)r / (double)NLON;
        const double scale = 6.283185307179586476925286766559 / (double)NLON;
        v = (float)(cos(theta) * scale);
    }
    sht_trig[idx] = v;
}

// ---------------------------------------------------------------
// Fold: xe[r][n'] = x[r][0] (n'=0), x[r][360] (n'=360),
//                   x[r][n'] + x[r][720-n'] (1<=n'<=359), 0 (pad)
// ---------------------------------------------------------------
__global__ void sht_fold(const float* __restrict__ x, unsigned xbud) {
    int idx = blockIdx.x * blockDim.x + threadIdx.x;
    if (idx >= NROWS * K1P) return;
    int r = idx / K1P;
    int n = idx - r * K1P;
    float v = 0.f;
    if (n <= 360) {
        unsigned b = (unsigned)r * NLON;
        unsigned i0 = b + (unsigned)n;
        float a = (i0 < xbud) ? x[i0] : 0.f;
        if (n >= 1 && n <= 359) {
            unsigned i1 = b + (unsigned)(NLON - n);
            a += (i1 < xbud) ? x[i1] : 0.f;
        }
        v = a;
    }
    sht_xe[idx] = v;
}

// ---------------------------------------------------------------
// Stage 1: xfr[m][r] = sum_{n'=0}^{360} xe[r][n'] * trig[n'][m]
// BM=128 rows, BN=64 m, BK=16 (23 iters exactly, pad-covered).
// 256 threads, 8x4 microtile, single accumulator set. grid=(361,6)
// ---------------------------------------------------------------
__global__ __launch_bounds__(256) void sht_stage1(int dummy) {
    __shared__ __align__(16) float As[16][132];   // [k][row]
    __shared__ __align__(16) float Bt[16][68];    // [k][m]

    const int tid  = threadIdx.x;
    const int row0 = blockIdx.x * 128;
    const int m0   = blockIdx.y * 64;
    const int tx   = tid & 15;
    const int ty   = tid >> 4;

    float acc[4][8];
#pragma unroll
    for (int j = 0; j < 4; j++)
#pragma unroll
        for (int i = 0; i < 8; i++) acc[j][i] = 0.f;

    const int a_row = tid >> 2;        // 0..63 (two row groups)
    const int a_kq  = (tid & 3) * 4;   // 0,4,8,12

    for (int kb = 0; kb < K1P; kb += 16) {
        // A: 128 rows x 16 k, float4 on own padded scratch
        const float* p0 = &sht_xe[(size_t)(row0 + a_row) * K1P + kb + a_kq];
        const float* p1 = &sht_xe[(size_t)(row0 + a_row + 64) * K1P + kb + a_kq];
        float4 v0 = *(const float4*)p0;
        float4 v1 = *(const float4*)p1;
        As[a_kq + 0][a_row] = v0.x; As[a_kq + 1][a_row] = v0.y;
        As[a_kq + 2][a_row] = v0.z; As[a_kq + 3][a_row] = v0.w;
        As[a_kq + 0][a_row + 64] = v1.x; As[a_kq + 1][a_row + 64] = v1.y;
        As[a_kq + 2][a_row + 64] = v1.z; As[a_kq + 3][a_row + 64] = v1.w;

        // B: 16 k x 64 m (scalar, m-guarded; k pad rows are zeros in table)
#pragma unroll
        for (int i = 0; i < 4; i++) {
            int f = tid + i * 256;
            int r = f >> 6;
            int c = f & 63;
            int m = m0 + c;
            Bt[r][c] = (m < MMAX) ? sht_trig[(kb + r) * MMAX + m] : 0.f;
        }
        __syncthreads();

#pragma unroll
        for (int kk = 0; kk < 16; kk++) {
            float4 a0 = *(const float4*)&As[kk][ty * 8];
            float4 a1 = *(const float4*)&As[kk][ty * 8 + 4];
            float4 b4 = *(const float4*)&Bt[kk][tx * 4];
            float a[8] = {a0.x, a0.y, a0.z, a0.w, a1.x, a1.y, a1.z, a1.w};
            float bv[4] = {b4.x, b4.y, b4.z, b4.w};
#pragma unroll
            for (int j = 0; j < 4; j++)
#pragma unroll
                for (int i = 0; i < 8; i++)
                    acc[j][i] = fmaf(a[i], bv[j], acc[j][i]);
        }
        __syncthreads();
    }

    // Store xfr[m][bc][368]: r -> (bc, k) with k = r % 361
#pragma unroll
    for (int j = 0; j < 4; j++) {
        int m = m0 + tx * 4 + j;
        if (m >= MMAX) continue;
        size_t mb = (size_t)m * BC * K1P;
#pragma unroll
        for (int i = 0; i < 8; i++) {
            int r  = row0 + ty * 8 + i;
            int bc = r / NLAT;
            int k  = r - bc * NLAT;
            sht_xfr[mb + (size_t)bc * K1P + k] = acc[j][i];
        }
    }
}

// ---------------------------------------------------------------
// Stage 2: out[(bc*360+l)*361+m] = sum_k xfr[m][bc][k] * w[m][l][k]
// BM=128 bc, BN=64 l, BK=16 (23 iters, xfr pad zeros cover k>=361,
// W guarded). 256 threads, 8x4 microtile. grid=(6,361)
// ---------------------------------------------------------------
__global__ __launch_bounds__(256) void sht_stage2(const float* __restrict__ w,
                                                  float* __restrict__ out,
                                                  unsigned wbud, unsigned obud) {
    __shared__ __align__(16) float As[16][132];   // [k][bc]
    __shared__ __align__(16) float Ws[16][68];    // [k][l]

    const int tid = threadIdx.x;
    const int m   = blockIdx.y;
    const int l0  = blockIdx.x * 64;
    const int tx  = tid & 15;
    const int ty  = tid >> 4;

    const float* __restrict__ xa = sht_xfr + (size_t)m * BC * K1P;

    float acc[4][8];
#pragma unroll
    for (int j = 0; j < 4; j++)
#pragma unroll
        for (int i = 0; i < 8; i++) acc[j][i] = 0.f;

    const int a_bc = tid >> 2;         // 0..63 (two bc groups)
    const int a_kq = (tid & 3) * 4;

    for (int kb = 0; kb < K1P; kb += 16) {
        // A: 128 bc x 16 k via float4 along k (padded, zeros beyond 361)
        float4 v0 = *(const float4*)&xa[(size_t)a_bc * K1P + kb + a_kq];
        float4 v1 = *(const float4*)&xa[(size_t)(a_bc + 64) * K1P + kb + a_kq];
        As[a_kq + 0][a_bc] = v0.x; As[a_kq + 1][a_bc] = v0.y;
        As[a_kq + 2][a_bc] = v0.z; As[a_kq + 3][a_bc] = v0.w;
        As[a_kq + 0][a_bc + 64] = v1.x; As[a_kq + 1][a_bc + 64] = v1.y;
        As[a_kq + 2][a_bc + 64] = v1.z; As[a_kq + 3][a_bc + 64] = v1.w;

        // W: 16 k x 64 l, scalar guarded
#pragma unroll
        for (int i = 0; i < 4; i++) {
            int f  = tid + i * 256;
            int l  = f >> 4;
            int kk = f & 15;
            int k  = kb + kk;
            int ll = l0 + l;
            float v = 0.f;
            if (k < NLAT && ll < LMAX) {
                unsigned gi = (unsigned)m * (LMAX * NLAT) + (unsigned)ll * NLAT + (unsigned)k;
                if (gi < wbud) v = w[gi];
            }
            Ws[kk][l] = v;
        }
        __syncthreads();

#pragma unroll
        for (int kk = 0; kk < 16; kk++) {
            float4 a0 = *(const float4*)&As[kk][ty * 8];
            float4 a1 = *(const float4*)&As[kk][ty * 8 + 4];
            float4 w4 = *(const float4*)&Ws[kk][tx * 4];
            float a[8] = {a0.x, a0.y, a0.z, a0.w, a1.x, a1.y, a1.z, a1.w};
            float wv[4] = {w4.x, w4.y, w4.z, w4.w};
#pragma unroll
            for (int j = 0; j < 4; j++)
#pragma unroll
                for (int i = 0; i < 8; i++)
                    acc[j][i] = fmaf(a[i], wv[j], acc[j][i]);
        }
        __syncthreads();
    }

    // Store real part: out[(bc*360 + l)*361 + m]
#pragma unroll
    for (int j = 0; j < 4; j++) {
        int l = l0 + tx * 4 + j;
        if (l >= LMAX) continue;
#pragma unroll
        for (int i = 0; i < 8; i++) {
            int bc = ty * 8 + i;
            unsigned ci = ((unsigned)bc * LMAX + (unsigned)l) * MMAX + (unsigned)m;
            if (ci < obud) out[ci] = acc[j][i];
        }
    }
}

// ---------------------------------------------------------------
extern "C" void kernel_launch(void* const* d_in, const int* in_sizes, int n_in,
                              void* d_out, int out_size) {
    const float* x = nullptr;
    const float* w = nullptr;
    unsigned xbud = 0, wbud = 0;

    for (int i = 0; i < n_in; i++) {
        if (in_sizes[i] == X_ELEMS && !x) { x = (const float*)d_in[i]; xbud = X_ELEMS; }
        else if (in_sizes[i] == W_ELEMS && !w) { w = (const float*)d_in[i]; wbud = W_ELEMS; }
    }
    if (!x && n_in >= 1) {
        x = (const float*)d_in[0];
        long s = in_sizes[0];
        xbud = (unsigned)((s > 0 && s < (long)X_ELEMS) ? s : X_ELEMS);
    }
    if (!w && n_in >= 2) {
        w = (const float*)d_in[1];
        long s = in_sizes[1];
        wbud = (unsigned)((s > 0 && s < (long)W_ELEMS) ? s : W_ELEMS);
    }

    unsigned obud;
    if (out_size <= 0) obud = OUT_REAL;
    else obud = ((unsigned)out_size < (unsigned)OUT_REAL) ? (unsigned)out_size
                                                          : (unsigned)OUT_REAL;

    float* out = (float*)d_out;

    sht_init_trig<<<(K1P * MMAX + 255) / 256, 256>>>();
    sht_fold<<<(NROWS * K1P + 255) / 256, 256>>>(x, xbud);
    sht_stage1<<<dim3(361, 6), 256>>>(0);
    sht_stage2<<<dim3(6, MMAX), 256>>>(w, out, wbud, obud);
}

// round 9
// speedup vs baseline: 3.7351x; 1.0476x over previous
#include <cuda_runtime.h>
#include <math.h>

// Problem constants
#define NLAT 361
#define NLON 720
#define MMAX 361            // NLON/2 + 1
#define LMAX 360            // NLAT - 1
#define BC   128            // batch*chan
#define NROWS (BC * NLAT)   // 46208 = 361 * 128

#define X_ELEMS  (BC * NLAT * NLON)         // 33,269,760
#define W_ELEMS  (MMAX * LMAX * NLAT)       // 46,915,560
#define OUT_REAL (BC * LMAX * MMAX)         // 16,634,880 float32 (real part)

#define K1  361             // folded DFT length
#define K1P 368             // padded to multiple of 16 (zeros in pad)

// -------- static device scratch (zero-initialized at load) --------
__device__ float sht_trig[K1P * MMAX];             // [n'][m], cos*scale, pad=0
__device__ float sht_xe[(size_t)NROWS * K1P];      // folded input [r][368]
__device__ float sht_xfr[(size_t)MMAX * BC * K1P]; // [m][bc][368] real spectra

// ---------------------------------------------------------------
__global__ void sht_init_trig() {
    int idx = blockIdx.x * blockDim.x + threadIdx.x;
    if (idx >= K1P * MMAX) return;
    int n = idx / MMAX;
    int m = idx - n * MMAX;
    float v = 0.f;
    if (n <= 360) {
        int r = (n * m) % NLON;
        double theta = 6.283185307179586476925286766559 * (double)r / (double)NLON;
        const double scale = 6.283185307179586476925286766559 / (double)NLON;
        v = (float)(cos(theta) * scale);
    }
    sht_trig[idx] = v;
}

// ---------------------------------------------------------------
__global__ void sht_fold(const float* __restrict__ x, unsigned xbud) {
    int idx = blockIdx.x * blockDim.x + threadIdx.x;
    if (idx >= NROWS * K1P) return;
    int r = idx / K1P;
    int n = idx - r * K1P;
    float v = 0.f;
    if (n <= 360) {
        unsigned b = (unsigned)r * NLON;
        unsigned i0 = b + (unsigned)n;
        float a = (i0 < xbud) ? x[i0] : 0.f;
        if (n >= 1 && n <= 359) {
            unsigned i1 = b + (unsigned)(NLON - n);
            a += (i1 < xbud) ? x[i1] : 0.f;
        }
        v = a;
    }
    sht_xe[idx] = v;
}

// ---------------------------------------------------------------
// Stage 1: xfr[m][r] = sum_k xe[r][k] * trig[k][m]
// 128x128 tile, BK=16, 256 threads, 8x8 split microtile. grid=(361,3)
// ---------------------------------------------------------------
__global__ __launch_bounds__(256, 2) void sht_stage1(int dummy) {
    __shared__ __align__(16) float As[16][132];   // [k][row]
    __shared__ __align__(16) float Bs[16][132];   // [k][m]

    const int tid  = threadIdx.x;
    const int row0 = blockIdx.x * 128;
    const int m0   = blockIdx.y * 128;
    const int tx   = tid & 15;
    const int ty   = tid >> 4;

    float acc[8][8];
#pragma unroll
    for (int j = 0; j < 8; j++)
#pragma unroll
        for (int i = 0; i < 8; i++) acc[j][i] = 0.f;

    const int a_row = tid >> 2;        // 0..63
    const int a_kq  = (tid & 3) * 4;   // 0,4,8,12

    for (int kb = 0; kb < K1P; kb += 16) {
        // A: 128 rows x 16 k (float4 on own padded scratch)
        float4 v0 = *(const float4*)&sht_xe[(size_t)(row0 + a_row) * K1P + kb + a_kq];
        float4 v1 = *(const float4*)&sht_xe[(size_t)(row0 + a_row + 64) * K1P + kb + a_kq];
        As[a_kq + 0][a_row] = v0.x; As[a_kq + 1][a_row] = v0.y;
        As[a_kq + 2][a_row] = v0.z; As[a_kq + 3][a_row] = v0.w;
        As[a_kq + 0][a_row + 64] = v1.x; As[a_kq + 1][a_row + 64] = v1.y;
        As[a_kq + 2][a_row + 64] = v1.z; As[a_kq + 3][a_row + 64] = v1.w;

        // B: 16 k x 128 m (coalesced scalar, m-guarded; pad k rows are 0)
#pragma unroll
        for (int i = 0; i < 8; i++) {
            int f = tid + i * 256;
            int r = f >> 7;        // 0..15
            int c = f & 127;       // 0..127
            int m = m0 + c;
            Bs[r][c] = (m < MMAX) ? sht_trig[(kb + r) * MMAX + m] : 0.f;
        }
        __syncthreads();

#pragma unroll
        for (int kk = 0; kk < 16; kk++) {
            float4 a0 = *(const float4*)&As[kk][ty * 4];
            float4 a1 = *(const float4*)&As[kk][ty * 4 + 64];
            float4 b0 = *(const float4*)&Bs[kk][tx * 4];
            float4 b1 = *(const float4*)&Bs[kk][tx * 4 + 64];
            float a[8] = {a0.x, a0.y, a0.z, a0.w, a1.x, a1.y, a1.z, a1.w};
            float b[8] = {b0.x, b0.y, b0.z, b0.w, b1.x, b1.y, b1.z, b1.w};
#pragma unroll
            for (int j = 0; j < 8; j++)
#pragma unroll
                for (int i = 0; i < 8; i++)
                    acc[j][i] = fmaf(a[i], b[j], acc[j][i]);
        }
        __syncthreads();
    }

    // Store xfr[m][bc][368]: r -> (bc = r/361, k = r%361)
#pragma unroll
    for (int j = 0; j < 8; j++) {
        int m = m0 + tx * 4 + (j & 3) + ((j >> 2) << 6);
        if (m >= MMAX) continue;
        size_t mb = (size_t)m * BC * K1P;
#pragma unroll
        for (int i = 0; i < 8; i++) {
            int r  = row0 + ty * 4 + (i & 3) + ((i >> 2) << 6);
            int bc = r / NLAT;
            int k  = r - bc * NLAT;
            sht_xfr[mb + (size_t)bc * K1P + k] = acc[j][i];
        }
    }
}

// ---------------------------------------------------------------
// Stage 2: out[(bc*360+l)*361+m] = sum_k xfr[m][bc][k] * w[m][l][k]
// 128(bc)x128(l) tile, BK=16, 256 threads, 8x8 split microtile. grid=(3,361)
// ---------------------------------------------------------------
__global__ __launch_bounds__(256, 2) void sht_stage2(const float* __restrict__ w,
                                                     float* __restrict__ out,
                                                     unsigned wbud, unsigned obud) {
    __shared__ __align__(16) float As[16][132];   // [k][bc]
    __shared__ __align__(16) float Ws[16][132];   // [k][l]

    const int tid = threadIdx.x;
    const int m   = blockIdx.y;
    const int l0  = blockIdx.x * 128;
    const int tx  = tid & 15;
    const int ty  = tid >> 4;

    const float* __restrict__ xa = sht_xfr + (size_t)m * BC * K1P;

    float acc[8][8];
#pragma unroll
    for (int j = 0; j < 8; j++)
#pragma unroll
        for (int i = 0; i < 8; i++) acc[j][i] = 0.f;

    const int a_bc = tid >> 2;
    const int a_kq = (tid & 3) * 4;

    for (int kb = 0; kb < K1P; kb += 16) {
        // A: 128 bc x 16 k via float4 (padded, zeros beyond 361)
        float4 v0 = *(const float4*)&xa[(size_t)a_bc * K1P + kb + a_kq];
        float4 v1 = *(const float4*)&xa[(size_t)(a_bc + 64) * K1P + kb + a_kq];
        As[a_kq + 0][a_bc] = v0.x; As[a_kq + 1][a_bc] = v0.y;
        As[a_kq + 2][a_bc] = v0.z; As[a_kq + 3][a_bc] = v0.w;
        As[a_kq + 0][a_bc + 64] = v1.x; As[a_kq + 1][a_bc + 64] = v1.y;
        As[a_kq + 2][a_bc + 64] = v1.z; As[a_kq + 3][a_bc + 64] = v1.w;

        // W: 16 k x 128 l, scalar (k-coalesced), guarded
#pragma unroll
        for (int i = 0; i < 8; i++) {
            int f  = tid + i * 256;
            int kk = f & 15;
            int l  = f >> 4;       // 0..127
            int k  = kb + kk;
            int ll = l0 + l;
            float v = 0.f;
            if (k < NLAT && ll < LMAX) {
                unsigned gi = (unsigned)m * (LMAX * NLAT) + (unsigned)ll * NLAT + (unsigned)k;
                if (gi < wbud) v = w[gi];
            }
            Ws[kk][l] = v;
        }
        __syncthreads();

#pragma unroll
        for (int kk = 0; kk < 16; kk++) {
            float4 a0 = *(const float4*)&As[kk][ty * 4];
            float4 a1 = *(const float4*)&As[kk][ty * 4 + 64];
            float4 w0 = *(const float4*)&Ws[kk][tx * 4];
            float4 w1 = *(const float4*)&Ws[kk][tx * 4 + 64];
            float a[8] = {a0.x, a0.y, a0.z, a0.w, a1.x, a1.y, a1.z, a1.w};
            float b[8] = {w0.x, w0.y, w0.z, w0.w, w1.x, w1.y, w1.z, w1.w};
#pragma unroll
            for (int j = 0; j < 8; j++)
#pragma unroll
                for (int i = 0; i < 8; i++)
                    acc[j][i] = fmaf(a[i], b[j], acc[j][i]);
        }
        __syncthreads();
    }

    // Store real part: out[(bc*360 + l)*361 + m]
#pragma unroll
    for (int j = 0; j < 8; j++) {
        int l = l0 + tx * 4 + (j & 3) + ((j >> 2) << 6);
        if (l >= LMAX) continue;
#pragma unroll
        for (int i = 0; i < 8; i++) {
            int bc = ty * 4 + (i & 3) + ((i >> 2) << 6);
            unsigned ci = ((unsigned)bc * LMAX + (unsigned)l) * MMAX + (unsigned)m;
            if (ci < obud) out[ci] = acc[j][i];
        }
    }
}

// ---------------------------------------------------------------
extern "C" void kernel_launch(void* const* d_in, const int* in_sizes, int n_in,
                              void* d_out, int out_size) {
    const float* x = nullptr;
    const float* w = nullptr;
    unsigned xbud = 0, wbud = 0;

    for (int i = 0; i < n_in; i++) {
        if (in_sizes[i] == X_ELEMS && !x) { x = (const float*)d_in[i]; xbud = X_ELEMS; }
        else if (in_sizes[i] == W_ELEMS && !w) { w = (const float*)d_in[i]; wbud = W_ELEMS; }
    }
    if (!x && n_in >= 1) {
        x = (const float*)d_in[0];
        long s = in_sizes[0];
        xbud = (unsigned)((s > 0 && s < (long)X_ELEMS) ? s : X_ELEMS);
    }
    if (!w && n_in >= 2) {
        w = (const float*)d_in[1];
        long s = in_sizes[1];
        wbud = (unsigned)((s > 0 && s < (long)W_ELEMS) ? s : W_ELEMS);
    }

    unsigned obud;
    if (out_size <= 0) obud = OUT_REAL;
    else obud = ((unsigned)out_size < (unsigned)OUT_REAL) ? (unsigned)out_size
                                                          : (unsigned)OUT_REAL;

    float* out = (float*)d_out;

    sht_init_trig<<<(K1P * MMAX + 255) / 256, 256>>>();
    sht_fold<<<(NROWS * K1P + 255) / 256, 256>>>(x, xbud);
    sht_stage1<<<dim3(361, 3), 256>>>(0);
    sht_stage2<<<dim3(3, MMAX), 256>>>(w, out, wbud, obud);
}